// round 11
// baseline (speedup 1.0000x reference)
#include <cuda_runtime.h>
#include <math.h>

// L=8,B=8,N=4,HIN=1024,D=1024,NH=16,KVH=8,HD=64,FF=3072,W=1024,DOUT=1024, M=B*N=32

__device__ float g_scratch[360448];
#define OFF_H    0
#define OFF_X    32768
#define OFF_QKV  65536
#define OFF_ATT  131072
#define OFF_GU   163840

__device__ __forceinline__ void ffma2(unsigned long long &a,
                                      unsigned long long x,
                                      unsigned long long w) {
    asm("fma.rn.f32x2 %0, %1, %2, %0;" : "+l"(a) : "l"(x), "l"(w));
}

__global__ void zero_kernel(float* p) {
    ((float4*)p)[blockIdx.x * 256 + threadIdx.x] = make_float4(0.f, 0.f, 0.f, 0.f);
}

// ---- RMSNorm over 1024 cols (+ zero an accumulator buffer)
__global__ void rms_kernel(const float* __restrict__ hin, const float* __restrict__ w,
                           float* __restrict__ xout, float* __restrict__ zbuf, int zn4) {
    __shared__ float sw[8];
    int m = blockIdx.x, tid = threadIdx.x;
    float4 v = ((const float4*)(hin + m * 1024))[tid];
    float ss = v.x * v.x + v.y * v.y + v.z * v.z + v.w * v.w;
    for (int o = 16; o; o >>= 1) ss += __shfl_xor_sync(~0u, ss, o);
    if ((tid & 31) == 0) sw[tid >> 5] = ss;
    __syncthreads();
    if (tid < 32) {
        float z = (tid < 8) ? sw[tid] : 0.f;
        for (int o = 4; o; o >>= 1) z += __shfl_xor_sync(~0u, z, o);
        if (tid == 0) sw[0] = z;
    }
    __syncthreads();
    float rs = rsqrtf(sw[0] * (1.0f / 1024.0f) + 1e-6f);
    float4 wv = ((const float4*)w)[tid];
    ((float4*)(xout + m * 1024))[tid] =
        make_float4(v.x * rs * wv.x, v.y * rs * wv.y, v.z * rs * wv.z, v.w * rs * wv.w);
    if (zbuf) {
        float4 zz = make_float4(0.f, 0.f, 0.f, 0.f);
        for (int i = m * 256 + tid; i < zn4; i += 8192) ((float4*)zbuf)[i] = zz;
    }
}

// ---- skinny GEMM v8 (cp.async multistage, deep prefetch distance)
// out[32,*] (+)= x[32,K] @ W[K,*]; 128 cols/block; 256 threads =
// 4 m-groups x 64 col-threads (2 cols each, f32x2). Weights global->smem via
// cp.async.cg, S stages of 8 k-rows (4KB), prefetch distance S-1 stages.
// Split-K grid.y, fp32 atomic epilogue. 3 col segments (b1,b2).
// uoff!=0 -> x = silu(g)*u. omode=1 -> transposed epilogue [B,DOUT,N].
template<int KC, int S>
__global__ __launch_bounds__(256, 4) void gemmcp(
    const float* __restrict__ xin, int xstride, int uoff,
    const float* __restrict__ w0, const float* __restrict__ w1, const float* __restrict__ w2,
    int ld0, int ld1, int ld2, int b1, int b2,
    float* __restrict__ out, int ostride, int omode) {
    constexpr int TOT = KC / 8;
    __shared__ __align__(16) float2 xs[32][KC];
    __shared__ __align__(16) float ws[S][8][128];

    int tid = threadIdx.x;
    int ct = tid & 63, mbase = (tid >> 6) << 3;
    int kk = tid >> 5, cc = tid & 31;
    int col0 = blockIdx.x * 128, kbase = blockIdx.y * KC;
    const float* w; int ld, c0;
    if (col0 < b1)      { w = w0; ld = ld0; c0 = col0; }
    else if (col0 < b2) { w = w1; ld = ld1; c0 = col0 - b1; }
    else                { w = w2; ld = ld2; c0 = col0 - b2; }

    auto fill = [&](int s, int st) {
        const float* src = w + (size_t)(kbase + st * 8 + kk) * ld + c0 + cc * 4;
        unsigned sd = (unsigned)__cvta_generic_to_shared(&ws[s][kk][cc * 4]);
        asm volatile("cp.async.cg.shared.global [%0], [%1], 16;" :: "r"(sd), "l"(src));
    };

#pragma unroll
    for (int s = 0; s < S - 1; s++) {
        if (s < TOT) fill(s, s);
        asm volatile("cp.async.commit_group;");
    }

    // stage x tile (optionally SwiGLU), duplicated pairs for f32x2
#pragma unroll 4
    for (int idx = tid; idx < 32 * KC; idx += 256) {
        int m = idx / KC, k = idx - m * KC;
        float v = xin[m * xstride + kbase + k];
        if (uoff) {
            float uu = xin[m * xstride + uoff + kbase + k];
            v = (v / (1.0f + expf(-v))) * uu;
        }
        xs[m][k] = make_float2(v, v);
    }

    unsigned long long acc[8];
#pragma unroll
    for (int m = 0; m < 8; m++) acc[m] = 0ull;

#pragma unroll 1
    for (int st = 0; st < TOT; st++) {
        asm volatile("cp.async.wait_group %0;" :: "n"(S - 2));
        __syncthreads();
        int ns = st + S - 1;
        if (ns < TOT) fill(ns % S, ns);
        asm volatile("cp.async.commit_group;");
        int s = st % S;
#pragma unroll
        for (int kp = 0; kp < 4; kp++) {
            unsigned long long wA = *(const unsigned long long*)&ws[s][2 * kp][2 * ct];
            unsigned long long wB = *(const unsigned long long*)&ws[s][2 * kp + 1][2 * ct];
            int kg = st * 4 + kp;
#pragma unroll
            for (int m = 0; m < 8; m++) {
                ulonglong2 xv = *(const ulonglong2*)&xs[mbase + m][2 * kg];
                ffma2(acc[m], xv.x, wA);
                ffma2(acc[m], xv.y, wB);
            }
        }
    }

#pragma unroll
    for (int m = 0; m < 8; m++) {
        float lo = __uint_as_float((unsigned)acc[m]);
        float hi = __uint_as_float((unsigned)(acc[m] >> 32));
        int mg = mbase + m, cg = col0 + 2 * ct;
        if (omode == 0) {
            atomicAdd(out + mg * ostride + cg, lo);
            atomicAdd(out + mg * ostride + cg + 1, hi);
        } else {
            int bb = mg >> 2, tt = mg & 3;
            atomicAdd(out + (bb * 1024 + cg) * 4 + tt, lo);
            atomicAdd(out + (bb * 1024 + cg + 1) * 4 + tt, hi);
        }
    }
}

// ---- fused attention: rope/rms for q,k + cache write + slab copy + attention
__global__ __launch_bounds__(256) void attn2(
    const float* __restrict__ qkvb, const float* __restrict__ pk,
    const float* __restrict__ pv, const float* __restrict__ qn,
    const float* __restrict__ kn, float* __restrict__ ks, float* __restrict__ vs,
    float* __restrict__ att, int l) {
    __shared__ __align__(16) float qs[4][64];
    __shared__ __align__(16) float knew[4][64];
    __shared__ __align__(16) float vnew[4][64];
    __shared__ float ps[4][1024];
    __shared__ float red[2048];
    __shared__ float smax[4], ssum[4], swarp[8];
    int tid = threadIdx.x, b = blockIdx.x >> 4, h = blockIdx.x & 15, kvh = h >> 1;
    int wid = tid >> 5, lane = tid & 31;
    size_t slab = ((size_t)((l * 8 + b) * 8 + kvh)) * 65536;

    {
        int t = wid & 3, m = b * 4 + t;
        float invf = 1.0f / powf(1.0e6f, (float)lane * (1.0f / 32.0f));
        float angf = (float)(1024 + t) * invf;
        double ad = (double)angf;
        float cc = (float)cos(ad), sn = (float)sin(ad);
        if (wid < 4) {
            const float* base = qkvb + m * 2048 + h * 64;
            float a = base[lane], bb2 = base[lane + 32];
            float sq = a * a + bb2 * bb2;
            for (int o = 16; o; o >>= 1) sq += __shfl_xor_sync(~0u, sq, o);
            float rs = rsqrtf(sq * (1.0f / 64.0f) + 1e-6f);
            float ya = a * rs * qn[lane], yb = bb2 * rs * qn[lane + 32];
            qs[t][lane] = ya * cc - yb * sn;
            qs[t][lane + 32] = yb * cc + ya * sn;
        } else {
            const float* base = qkvb + m * 2048 + 1024 + kvh * 64;
            float a = base[lane], bb2 = base[lane + 32];
            float sq = a * a + bb2 * bb2;
            for (int o = 16; o; o >>= 1) sq += __shfl_xor_sync(~0u, sq, o);
            float rs = rsqrtf(sq * (1.0f / 64.0f) + 1e-6f);
            float ya = a * rs * kn[lane], yb = bb2 * rs * kn[lane + 32];
            float oa = ya * cc - yb * sn, ob = yb * cc + ya * sn;
            knew[t][lane] = oa; knew[t][lane + 32] = ob;
            const float* vb = qkvb + m * 2048 + 1536 + kvh * 64;
            float va = vb[lane], v2 = vb[lane + 32];
            vnew[t][lane] = va; vnew[t][lane + 32] = v2;
            size_t off = slab + (size_t)(1020 + t) * 64;
            if ((h & 1) == 0) { ks[off + lane] = oa; ks[off + lane + 32] = ob; }
            else              { vs[off + lane] = va; vs[off + lane + 32] = v2; }
        }
    }
    __syncthreads();

    const float* kcp = pk + slab + 256;
    bool doK = ((h & 1) == 0);
    float* kout = ks + slab;

    for (int r = 0; r < 4; r++) {
        int j = tid + (r << 8);
        const float4* kp4 = (j < 1020) ? (const float4*)(kcp + (size_t)j * 64)
                                       : (const float4*)(&knew[j - 1020][0]);
        float4* ko4 = (float4*)(kout + (size_t)j * 64);
        bool wr = doK && (j < 1020);
        float a0 = 0.f, a1 = 0.f, a2 = 0.f, a3 = 0.f;
#pragma unroll
        for (int d4 = 0; d4 < 16; d4++) {
            float4 kv = kp4[d4];
            if (wr) ko4[d4] = kv;
            float4 q0 = *(const float4*)&qs[0][d4 * 4];
            float4 q1 = *(const float4*)&qs[1][d4 * 4];
            float4 q2 = *(const float4*)&qs[2][d4 * 4];
            float4 q3 = *(const float4*)&qs[3][d4 * 4];
            a0 += kv.x * q0.x + kv.y * q0.y + kv.z * q0.z + kv.w * q0.w;
            a1 += kv.x * q1.x + kv.y * q1.y + kv.z * q1.z + kv.w * q1.w;
            a2 += kv.x * q2.x + kv.y * q2.y + kv.z * q2.z + kv.w * q2.w;
            a3 += kv.x * q3.x + kv.y * q3.y + kv.z * q3.z + kv.w * q3.w;
        }
        ps[0][j] = a0 * 0.125f + ((j <= 1020) ? 0.f : -10000.f);
        ps[1][j] = a1 * 0.125f + ((j <= 1021) ? 0.f : -10000.f);
        ps[2][j] = a2 * 0.125f + ((j <= 1022) ? 0.f : -10000.f);
        ps[3][j] = a3 * 0.125f;
    }
    __syncthreads();

    for (int t = 0; t < 4; t++) {
        float v = -1e30f;
        for (int j = tid; j < 1024; j += 256) v = fmaxf(v, ps[t][j]);
        for (int o = 16; o; o >>= 1) v = fmaxf(v, __shfl_xor_sync(~0u, v, o));
        if (lane == 0) swarp[wid] = v;
        __syncthreads();
        if (tid == 0) { float z = swarp[0]; for (int i = 1; i < 8; i++) z = fmaxf(z, swarp[i]); smax[t] = z; }
        __syncthreads();
    }
    float psum[4] = {0.f, 0.f, 0.f, 0.f};
    for (int t = 0; t < 4; t++)
        for (int j = tid; j < 1024; j += 256) {
            float e = expf(ps[t][j] - smax[t]);
            ps[t][j] = e; psum[t] += e;
        }
    for (int t = 0; t < 4; t++) {
        float v = psum[t];
        for (int o = 16; o; o >>= 1) v += __shfl_xor_sync(~0u, v, o);
        if (lane == 0) swarp[wid] = v;
        __syncthreads();
        if (tid == 0) { float z = 0.f; for (int i = 0; i < 8; i++) z += swarp[i]; ssum[t] = z; }
        __syncthreads();
    }
    {
        int u = tid & 31, s = tid >> 5;
        const float2* vcp = (const float2*)(pv + slab + 256);
        float2* vout = (float2*)(vs + slab);
        bool doV = ((h & 1) != 0);
        float oo[4][2] = {{0,0},{0,0},{0,0},{0,0}};
        for (int j = s * 128; j < s * 128 + 128; j++) {
            float2 v2 = (j < 1020) ? vcp[(size_t)j * 32 + u]
                                   : ((const float2*)vnew)[(j - 1020) * 32 + u];
            if (doV && j < 1020) vout[(size_t)j * 32 + u] = v2;
#pragma unroll
            for (int t = 0; t < 4; t++) { oo[t][0] += ps[t][j] * v2.x; oo[t][1] += ps[t][j] * v2.y; }
        }
#pragma unroll
        for (int t = 0; t < 4; t++) {
            red[((s * 4 + t) * 32 + u) * 2 + 0] = oo[t][0];
            red[((s * 4 + t) * 32 + u) * 2 + 1] = oo[t][1];
        }
    }
    __syncthreads();
    {
        int t = tid >> 6, d = tid & 63, u = d >> 1, c = d & 1;
        float z = 0.f;
#pragma unroll
        for (int si = 0; si < 8; si++) z += red[((si * 4 + t) * 32 + u) * 2 + c];
        att[(b * 4 + t) * 1024 + h * 64 + d] = z / ssum[t];
    }
}

extern "C" void kernel_launch(void* const* d_in, const int* in_sizes, int n_in,
                              void* d_out, int out_size) {
    const float* hidden = (const float*)d_in[0];
    const float* pk     = (const float*)d_in[1];
    const float* pv     = (const float*)d_in[2];
    const float* Win    = (const float*)d_in[3];
    const float* Wout   = (const float*)d_in[4];
    const float* normw  = (const float*)d_in[5];
    const float* Wq     = (const float*)d_in[6];
    const float* Wk     = (const float*)d_in[7];
    const float* Wv     = (const float*)d_in[8];
    const float* Wo     = (const float*)d_in[9];
    const float* ln1    = (const float*)d_in[10];
    const float* ln2    = (const float*)d_in[11];
    const float* qn     = (const float*)d_in[12];
    const float* kn     = (const float*)d_in[13];
    const float* Wg     = (const float*)d_in[14];
    const float* Wu     = (const float*)d_in[15];
    const float* Wd     = (const float*)d_in[16];

    float* outp = (float*)d_out;
    float* oh  = outp;
    float* oks = outp + 32768;
    float* ovs = outp + 32768 + 33554432;

    float* sc = 0;
    cudaGetSymbolAddress((void**)&sc, g_scratch);
    float* h   = sc + OFF_H;
    float* x   = sc + OFF_X;
    float* qkv = sc + OFF_QKV;
    float* att = sc + OFF_ATT;
    float* gu  = sc + OFF_GU;
    const int BIG = 1 << 30;

    zero_kernel<<<32, 256>>>(h);
    gemmcp<32, 5><<<dim3(8, 32), 256>>>(hidden, 1024, 0, Win, Win, Win,
        1024, 1024, 1024, BIG, BIG, h, 1024, 0);

    for (int l = 0; l < 8; l++) {
        rms_kernel<<<32, 256>>>(h, ln1 + l * 1024, x, qkv, 16384);
        gemmcp<64, 7><<<dim3(16, 16), 256>>>(x, 1024, 0,
            Wq + (size_t)l * 1048576, Wk + (size_t)l * 524288, Wv + (size_t)l * 524288,
            1024, 512, 512, 1024, 1536, qkv, 2048, 0);
        attn2<<<128, 256>>>(qkv, pk, pv, qn + l * 64, kn + l * 64, oks, ovs, att, l);
        gemmcp<32, 5><<<dim3(8, 32), 256>>>(att, 1024, 0,
            Wo + (size_t)l * 1048576, Wo, Wo, 1024, 1024, 1024, BIG, BIG, h, 1024, 0);
        rms_kernel<<<32, 256>>>(h, ln2 + l * 1024, x, gu, 49152);
        gemmcp<64, 7><<<dim3(48, 16), 256>>>(x, 1024, 0,
            Wg + (size_t)l * 3145728, Wu + (size_t)l * 3145728, Wu,
            3072, 3072, 3072, 3072, BIG, gu, 6144, 0);
        gemmcp<64, 7><<<dim3(8, 48), 256>>>(gu, 6144, 3072,
            Wd + (size_t)l * 3145728, Wd, Wd, 1024, 1024, 1024, BIG, BIG, h, 1024, 0);
    }

    rms_kernel<<<32, 256>>>(h, normw, x, oh, 8192);
    gemmcp<32, 5><<<dim3(8, 32), 256>>>(x, 1024, 0, Wout, Wout, Wout,
        1024, 1024, 1024, BIG, BIG, oh, 1024, 1);
}

// round 12
// speedup vs baseline: 1.1792x; 1.1792x over previous
#include <cuda_runtime.h>
#include <math.h>

// L=8,B=8,N=4,HIN=1024,D=1024,NH=16,KVH=8,HD=64,FF=3072,W=1024,DOUT=1024, M=B*N=32

__device__ float g_scratch[360448];
#define OFF_H    0
#define OFF_X    32768
#define OFF_QKV  65536
#define OFF_ATT  131072
#define OFF_GU   163840

__global__ void zero_kernel(float* p) {
    ((float4*)p)[blockIdx.x * 256 + threadIdx.x] = make_float4(0.f, 0.f, 0.f, 0.f);
}

// ---- RMSNorm over 1024 cols (+ zero an accumulator buffer)
__global__ void rms_kernel(const float* __restrict__ hin, const float* __restrict__ w,
                           float* __restrict__ xout, float* __restrict__ zbuf, int zn4) {
    __shared__ float sw[8];
    int m = blockIdx.x, tid = threadIdx.x;
    float4 v = ((const float4*)(hin + m * 1024))[tid];
    float ss = v.x * v.x + v.y * v.y + v.z * v.z + v.w * v.w;
    for (int o = 16; o; o >>= 1) ss += __shfl_xor_sync(~0u, ss, o);
    if ((tid & 31) == 0) sw[tid >> 5] = ss;
    __syncthreads();
    if (tid < 32) {
        float z = (tid < 8) ? sw[tid] : 0.f;
        for (int o = 4; o; o >>= 1) z += __shfl_xor_sync(~0u, z, o);
        if (tid == 0) sw[0] = z;
    }
    __syncthreads();
    float rs = rsqrtf(sw[0] * (1.0f / 1024.0f) + 1e-6f);
    float4 wv = ((const float4*)w)[tid];
    ((float4*)(xout + m * 1024))[tid] =
        make_float4(v.x * rs * wv.x, v.y * rs * wv.y, v.z * rs * wv.z, v.w * rs * wv.w);
    if (zbuf) {
        float4 zz = make_float4(0.f, 0.f, 0.f, 0.f);
        for (int i = m * 256 + tid; i < zn4; i += 8192) ((float4*)zbuf)[i] = zz;
    }
}

__device__ __forceinline__ unsigned tf32_rna(float v) {
    unsigned r; asm("cvt.rna.tf32.f32 %0, %1;" : "=r"(r) : "f"(v)); return r;
}

#define MMA_TF32(C, A0, A1, A2, A3, B0, B1)                                  \
    asm("mma.sync.aligned.m16n8k8.row.col.f32.tf32.tf32.f32 "                \
        "{%0,%1,%2,%3},{%4,%5,%6,%7},{%8,%9},{%0,%1,%2,%3};"                 \
        : "+f"(C[0]), "+f"(C[1]), "+f"(C[2]), "+f"(C[3])                      \
        : "r"(A0), "r"(A1), "r"(A2), "r"(A3), "r"(B0), "r"(B1))

// ---- skinny GEMM v9 (tensor-core 3xTF32, cp.async multistage)
// out[32,*] (+)= x[32,K] @ W[K,*]; 128 cols/block; 8 warps, each warp owns a
// 16-col slice x 32 rows via 4x m16n8k8 tiles per k8-step, 3 mma each
// (hi*hi, hi*lo, lo*hi) for fp32-grade accuracy. Weights: cp.async pipeline
// (S stages x 8 k-rows, padded rows vs bank conflicts). x pre-split hi/lo in
// smem. Split-K grid.y, fp32 atomic epilogue. 3 col segments (b1,b2).
// uoff!=0 -> x = silu(g)*u. omode=1 -> transposed epilogue [B,DOUT,N].
template<int KC, int S>
__global__ __launch_bounds__(256, 4) void gemmtc(
    const float* __restrict__ xin, int xstride, int uoff,
    const float* __restrict__ w0, const float* __restrict__ w1, const float* __restrict__ w2,
    int ld0, int ld1, int ld2, int b1, int b2,
    float* __restrict__ out, int ostride, int omode) {
    constexpr int TOT = KC / 8;
    constexpr int XR = KC + 4;                 // x row stride (banks: 4g+t distinct)
    __shared__ __align__(16) unsigned xh[32 * XR];
    __shared__ __align__(16) unsigned xl[32 * XR];
    __shared__ __align__(16) float ws[S][8 * 136];  // 136-stride: banks 8t+g distinct

    int tid = threadIdx.x, wp = tid >> 5, lane = tid & 31;
    int g = lane >> 2, t = lane & 3;
    int kk = tid >> 5, cc = tid & 31;
    int col0 = blockIdx.x * 128, kbase = blockIdx.y * KC;
    const float* w; int ld, c0;
    if (col0 < b1)      { w = w0; ld = ld0; c0 = col0; }
    else if (col0 < b2) { w = w1; ld = ld1; c0 = col0 - b1; }
    else                { w = w2; ld = ld2; c0 = col0 - b2; }

    auto fill = [&](int s, int st) {
        const float* src = w + (size_t)(kbase + st * 8 + kk) * ld + c0 + cc * 4;
        unsigned sd = (unsigned)__cvta_generic_to_shared(&ws[s][kk * 136 + cc * 4]);
        asm volatile("cp.async.cg.shared.global [%0], [%1], 16;" :: "r"(sd), "l"(src));
    };

#pragma unroll
    for (int s = 0; s < S - 1; s++) {
        if (s < TOT) fill(s, s);
        asm volatile("cp.async.commit_group;");
    }

    // stage x hi/lo tf32 split (optionally SwiGLU)
#pragma unroll 4
    for (int idx = tid; idx < 32 * KC; idx += 256) {
        int m = idx / KC, k = idx - m * KC;
        float v = xin[m * xstride + kbase + k];
        if (uoff) {
            float uu = xin[m * xstride + uoff + kbase + k];
            v = (v / (1.0f + expf(-v))) * uu;
        }
        unsigned hb = tf32_rna(v);
        float vl = v - __uint_as_float(hb);
        xh[m * XR + k] = hb;
        xl[m * XR + k] = tf32_rna(vl);
    }

    float c[4][4];
#pragma unroll
    for (int mt = 0; mt < 4; mt++)
#pragma unroll
        for (int i = 0; i < 4; i++) c[mt][i] = 0.f;

    int cw = wp * 16;

#pragma unroll 1
    for (int st = 0; st < TOT; st++) {
        asm volatile("cp.async.wait_group %0;" :: "n"(S - 2));
        __syncthreads();
        int ns = st + S - 1;
        if (ns < TOT) fill(ns % S, ns);
        asm volatile("cp.async.commit_group;");
        const float* wsp = ws[st % S];

        float wv0 = wsp[t * 136 + cw + g];
        float wv1 = wsp[t * 136 + cw + g + 8];
        float wv2 = wsp[(t + 4) * 136 + cw + g];
        float wv3 = wsp[(t + 4) * 136 + cw + g + 8];
        unsigned ah0 = tf32_rna(wv0), ah1 = tf32_rna(wv1);
        unsigned ah2 = tf32_rna(wv2), ah3 = tf32_rna(wv3);
        unsigned al0 = tf32_rna(wv0 - __uint_as_float(ah0));
        unsigned al1 = tf32_rna(wv1 - __uint_as_float(ah1));
        unsigned al2 = tf32_rna(wv2 - __uint_as_float(ah2));
        unsigned al3 = tf32_rna(wv3 - __uint_as_float(ah3));

        int kb = st * 8;
#pragma unroll
        for (int mt = 0; mt < 4; mt++) {
            int xr = (mt * 8 + g) * XR + kb;
            unsigned bh0 = xh[xr + t], bh1 = xh[xr + t + 4];
            unsigned bl0 = xl[xr + t], bl1 = xl[xr + t + 4];
            MMA_TF32(c[mt], ah0, ah1, ah2, ah3, bl0, bl1);
            MMA_TF32(c[mt], al0, al1, al2, al3, bh0, bh1);
            MMA_TF32(c[mt], ah0, ah1, ah2, ah3, bh0, bh1);
        }
    }

    // epilogue: D row = out-col, D col = out-row
#pragma unroll
    for (int mt = 0; mt < 4; mt++) {
        int r0 = mt * 8 + 2 * t;
        int cA = col0 + cw + g;
#pragma unroll
        for (int i = 0; i < 4; i++) {
            int row = r0 + (i & 1);
            int col = cA + (i >> 1) * 8;
            if (omode == 0) {
                atomicAdd(out + row * ostride + col, c[mt][i]);
            } else {
                int bb = row >> 2, tt = row & 3;
                atomicAdd(out + (bb * 1024 + col) * 4 + tt, c[mt][i]);
            }
        }
    }
}

// ---- fused attention: rope/rms for q,k + cache write + slab copy + attention
__global__ __launch_bounds__(256) void attn2(
    const float* __restrict__ qkvb, const float* __restrict__ pk,
    const float* __restrict__ pv, const float* __restrict__ qn,
    const float* __restrict__ kn, float* __restrict__ ks, float* __restrict__ vs,
    float* __restrict__ att, int l) {
    __shared__ __align__(16) float qs[4][64];
    __shared__ __align__(16) float knew[4][64];
    __shared__ __align__(16) float vnew[4][64];
    __shared__ float ps[4][1024];
    __shared__ float red[2048];
    __shared__ float smax[4], ssum[4], swarp[8];
    int tid = threadIdx.x, b = blockIdx.x >> 4, h = blockIdx.x & 15, kvh = h >> 1;
    int wid = tid >> 5, lane = tid & 31;
    size_t slab = ((size_t)((l * 8 + b) * 8 + kvh)) * 65536;

    {
        int t = wid & 3, m = b * 4 + t;
        float invf = 1.0f / powf(1.0e6f, (float)lane * (1.0f / 32.0f));
        float angf = (float)(1024 + t) * invf;
        double ad = (double)angf;
        float cc = (float)cos(ad), sn = (float)sin(ad);
        if (wid < 4) {
            const float* base = qkvb + m * 2048 + h * 64;
            float a = base[lane], bb2 = base[lane + 32];
            float sq = a * a + bb2 * bb2;
            for (int o = 16; o; o >>= 1) sq += __shfl_xor_sync(~0u, sq, o);
            float rs = rsqrtf(sq * (1.0f / 64.0f) + 1e-6f);
            float ya = a * rs * qn[lane], yb = bb2 * rs * qn[lane + 32];
            qs[t][lane] = ya * cc - yb * sn;
            qs[t][lane + 32] = yb * cc + ya * sn;
        } else {
            const float* base = qkvb + m * 2048 + 1024 + kvh * 64;
            float a = base[lane], bb2 = base[lane + 32];
            float sq = a * a + bb2 * bb2;
            for (int o = 16; o; o >>= 1) sq += __shfl_xor_sync(~0u, sq, o);
            float rs = rsqrtf(sq * (1.0f / 64.0f) + 1e-6f);
            float ya = a * rs * kn[lane], yb = bb2 * rs * kn[lane + 32];
            float oa = ya * cc - yb * sn, ob = yb * cc + ya * sn;
            knew[t][lane] = oa; knew[t][lane + 32] = ob;
            const float* vb = qkvb + m * 2048 + 1536 + kvh * 64;
            float va = vb[lane], v2 = vb[lane + 32];
            vnew[t][lane] = va; vnew[t][lane + 32] = v2;
            size_t off = slab + (size_t)(1020 + t) * 64;
            if ((h & 1) == 0) { ks[off + lane] = oa; ks[off + lane + 32] = ob; }
            else              { vs[off + lane] = va; vs[off + lane + 32] = v2; }
        }
    }
    __syncthreads();

    const float* kcp = pk + slab + 256;
    bool doK = ((h & 1) == 0);
    float* kout = ks + slab;

    for (int r = 0; r < 4; r++) {
        int j = tid + (r << 8);
        const float4* kp4 = (j < 1020) ? (const float4*)(kcp + (size_t)j * 64)
                                       : (const float4*)(&knew[j - 1020][0]);
        float4* ko4 = (float4*)(kout + (size_t)j * 64);
        bool wr = doK && (j < 1020);
        float a0 = 0.f, a1 = 0.f, a2 = 0.f, a3 = 0.f;
#pragma unroll
        for (int d4 = 0; d4 < 16; d4++) {
            float4 kv = kp4[d4];
            if (wr) ko4[d4] = kv;
            float4 q0 = *(const float4*)&qs[0][d4 * 4];
            float4 q1 = *(const float4*)&qs[1][d4 * 4];
            float4 q2 = *(const float4*)&qs[2][d4 * 4];
            float4 q3 = *(const float4*)&qs[3][d4 * 4];
            a0 += kv.x * q0.x + kv.y * q0.y + kv.z * q0.z + kv.w * q0.w;
            a1 += kv.x * q1.x + kv.y * q1.y + kv.z * q1.z + kv.w * q1.w;
            a2 += kv.x * q2.x + kv.y * q2.y + kv.z * q2.z + kv.w * q2.w;
            a3 += kv.x * q3.x + kv.y * q3.y + kv.z * q3.z + kv.w * q3.w;
        }
        ps[0][j] = a0 * 0.125f + ((j <= 1020) ? 0.f : -10000.f);
        ps[1][j] = a1 * 0.125f + ((j <= 1021) ? 0.f : -10000.f);
        ps[2][j] = a2 * 0.125f + ((j <= 1022) ? 0.f : -10000.f);
        ps[3][j] = a3 * 0.125f;
    }
    __syncthreads();

    for (int t = 0; t < 4; t++) {
        float v = -1e30f;
        for (int j = tid; j < 1024; j += 256) v = fmaxf(v, ps[t][j]);
        for (int o = 16; o; o >>= 1) v = fmaxf(v, __shfl_xor_sync(~0u, v, o));
        if (lane == 0) swarp[wid] = v;
        __syncthreads();
        if (tid == 0) { float z = swarp[0]; for (int i = 1; i < 8; i++) z = fmaxf(z, swarp[i]); smax[t] = z; }
        __syncthreads();
    }
    float psum[4] = {0.f, 0.f, 0.f, 0.f};
    for (int t = 0; t < 4; t++)
        for (int j = tid; j < 1024; j += 256) {
            float e = expf(ps[t][j] - smax[t]);
            ps[t][j] = e; psum[t] += e;
        }
    for (int t = 0; t < 4; t++) {
        float v = psum[t];
        for (int o = 16; o; o >>= 1) v += __shfl_xor_sync(~0u, v, o);
        if (lane == 0) swarp[wid] = v;
        __syncthreads();
        if (tid == 0) { float z = 0.f; for (int i = 0; i < 8; i++) z += swarp[i]; ssum[t] = z; }
        __syncthreads();
    }
    {
        int u = tid & 31, s = tid >> 5;
        const float2* vcp = (const float2*)(pv + slab + 256);
        float2* vout = (float2*)(vs + slab);
        bool doV = ((h & 1) != 0);
        float oo[4][2] = {{0,0},{0,0},{0,0},{0,0}};
        for (int j = s * 128; j < s * 128 + 128; j++) {
            float2 v2 = (j < 1020) ? vcp[(size_t)j * 32 + u]
                                   : ((const float2*)vnew)[(j - 1020) * 32 + u];
            if (doV && j < 1020) vout[(size_t)j * 32 + u] = v2;
#pragma unroll
            for (int t = 0; t < 4; t++) { oo[t][0] += ps[t][j] * v2.x; oo[t][1] += ps[t][j] * v2.y; }
        }
#pragma unroll
        for (int t = 0; t < 4; t++) {
            red[((s * 4 + t) * 32 + u) * 2 + 0] = oo[t][0];
            red[((s * 4 + t) * 32 + u) * 2 + 1] = oo[t][1];
        }
    }
    __syncthreads();
    {
        int t = tid >> 6, d = tid & 63, u = d >> 1, c = d & 1;
        float z = 0.f;
#pragma unroll
        for (int si = 0; si < 8; si++) z += red[((si * 4 + t) * 32 + u) * 2 + c];
        att[(b * 4 + t) * 1024 + h * 64 + d] = z / ssum[t];
    }
}

extern "C" void kernel_launch(void* const* d_in, const int* in_sizes, int n_in,
                              void* d_out, int out_size) {
    const float* hidden = (const float*)d_in[0];
    const float* pk     = (const float*)d_in[1];
    const float* pv     = (const float*)d_in[2];
    const float* Win    = (const float*)d_in[3];
    const float* Wout   = (const float*)d_in[4];
    const float* normw  = (const float*)d_in[5];
    const float* Wq     = (const float*)d_in[6];
    const float* Wk     = (const float*)d_in[7];
    const float* Wv     = (const float*)d_in[8];
    const float* Wo     = (const float*)d_in[9];
    const float* ln1    = (const float*)d_in[10];
    const float* ln2    = (const float*)d_in[11];
    const float* qn     = (const float*)d_in[12];
    const float* kn     = (const float*)d_in[13];
    const float* Wg     = (const float*)d_in[14];
    const float* Wu     = (const float*)d_in[15];
    const float* Wd     = (const float*)d_in[16];

    float* outp = (float*)d_out;
    float* oh  = outp;
    float* oks = outp + 32768;
    float* ovs = outp + 32768 + 33554432;

    float* sc = 0;
    cudaGetSymbolAddress((void**)&sc, g_scratch);
    float* h   = sc + OFF_H;
    float* x   = sc + OFF_X;
    float* qkv = sc + OFF_QKV;
    float* att = sc + OFF_ATT;
    float* gu  = sc + OFF_GU;
    const int BIG = 1 << 30;

    zero_kernel<<<32, 256>>>(h);
    gemmtc<32, 4><<<dim3(8, 32), 256>>>(hidden, 1024, 0, Win, Win, Win,
        1024, 1024, 1024, BIG, BIG, h, 1024, 0);

    for (int l = 0; l < 8; l++) {
        rms_kernel<<<32, 256>>>(h, ln1 + l * 1024, x, qkv, 16384);
        gemmtc<64, 5><<<dim3(16, 16), 256>>>(x, 1024, 0,
            Wq + (size_t)l * 1048576, Wk + (size_t)l * 524288, Wv + (size_t)l * 524288,
            1024, 512, 512, 1024, 1536, qkv, 2048, 0);
        attn2<<<128, 256>>>(qkv, pk, pv, qn + l * 64, kn + l * 64, oks, ovs, att, l);
        gemmtc<32, 4><<<dim3(8, 32), 256>>>(att, 1024, 0,
            Wo + (size_t)l * 1048576, Wo, Wo, 1024, 1024, 1024, BIG, BIG, h, 1024, 0);
        rms_kernel<<<32, 256>>>(h, ln2 + l * 1024, x, gu, 49152);
        gemmtc<64, 5><<<dim3(48, 16), 256>>>(x, 1024, 0,
            Wg + (size_t)l * 3145728, Wu + (size_t)l * 3145728, Wu,
            3072, 3072, 3072, 3072, BIG, gu, 6144, 0);
        gemmtc<64, 5><<<dim3(8, 48), 256>>>(gu, 6144, 3072,
            Wd + (size_t)l * 3145728, Wd, Wd, 1024, 1024, 1024, BIG, BIG, h, 1024, 0);
    }

    rms_kernel<<<32, 256>>>(h, normw, x, oh, 8192);
    gemmtc<32, 4><<<dim3(8, 32), 256>>>(x, 1024, 0, Wout, Wout, Wout,
        1024, 1024, 1024, BIG, BIG, oh, 1024, 1);
}